// round 16
// baseline (speedup 1.0000x reference)
#include <cuda_runtime.h>
#include <cuda_fp16.h>
#include <cstdint>
#include <math.h>

#define Bb 4
#define Ll 16384
#define Cc 512
#define Hh 8
#define Dd 64
#define MM (Bb*Ll)      // 65536
#define BHn (Bb*Hh)     // 32

// Stage-1: 128x128 tile, BK=64, 3 stages, 2 CTA/SM, 256 threads (warp tile 32x64)
#define QSTAGE 32768     // A 16K | B 16K
#define QSMEM (3*QSTAGE)
#define QNIT 8           // 512/64

// kv_tc smem: stage = K 8K | V 8K = 16K, 3 stages
#define KV_STAGE 16384
#define KV_SMEM (3*KV_STAGE)
// out_tc smem: Q 16K | B 10K
#define OUT_SMEM (16384 + 10240)

// fused prep grid split
#define PREP_X_BLOCKS 32768          // MM*Cc/1024
#define PREP_W_BLOCKS 192            // 3 z * 64 (64x64) tiles
#define PREP_Z_BLOCKS 520
#define PREP_GRID (PREP_X_BLOCKS + PREP_W_BLOCKS + PREP_Z_BLOCKS)

// Scratch (all fp16)
__device__ __half g_Xh[(size_t)MM*Cc];            // X
__device__ __half g_Wth[3*(size_t)Cc*Cc];         // W^T, [z][n][k]
__device__ __half g_Q [(size_t)MM*Cc];            // feature-mapped Q
__device__ __half g_K [(size_t)MM*Cc];            // feature-mapped K
__device__ __half g_V [(size_t)MM*Cc];            // V
__device__ float g_KV[BHn*Dd*Dd];
__device__ float g_Ksum[BHn*Dd];
__device__ __half g_KVt[(size_t)BHn*80*64];       // [bh][v-row(80)][d], row64=Ksum
__device__ int g_cnt[BHn];                        // kv_tc completion counters

// ---------------------------------------------------------------------------
__device__ __forceinline__ uint32_t smem_u32(const void* p) {
    uint32_t a;
    asm("{ .reg .u64 t; cvta.to.shared.u64 t, %1; cvt.u32.u64 %0, t; }" : "=r"(a) : "l"(p));
    return a;
}
#define SWZ128(o) ((o) ^ (((o) >> 3) & 0x70))

__device__ __forceinline__ void cpa16(uint32_t d, const void* s) {
    uint64_t gp;
    asm("cvta.to.global.u64 %0, %1;" : "=l"(gp) : "l"(s));
    asm volatile("cp.async.cg.shared.global [%0], [%1], 16;" :: "r"(d), "l"(gp) : "memory");
}
__device__ __forceinline__ void cp_commit() {
    asm volatile("cp.async.commit_group;" ::: "memory");
}
template<int N> __device__ __forceinline__ void cp_wait() {
    asm volatile("cp.async.wait_group %0;" :: "n"(N) : "memory");
}
__device__ __forceinline__ void ldm4(uint32_t* r, uint32_t a) {
    asm volatile("ldmatrix.sync.aligned.m8n8.x4.shared.b16 {%0,%1,%2,%3}, [%4];"
        : "=r"(r[0]), "=r"(r[1]), "=r"(r[2]), "=r"(r[3]) : "r"(a));
}
__device__ __forceinline__ void ldm4t(uint32_t* r, uint32_t a) {
    asm volatile("ldmatrix.sync.aligned.m8n8.x4.trans.shared.b16 {%0,%1,%2,%3}, [%4];"
        : "=r"(r[0]), "=r"(r[1]), "=r"(r[2]), "=r"(r[3]) : "r"(a));
}
__device__ __forceinline__ void mma16816h(float* c, const uint32_t* a, const uint32_t* b) {
    asm volatile("mma.sync.aligned.m16n8k16.row.col.f32.f16.f16.f32 "
        "{%0,%1,%2,%3}, {%4,%5,%6,%7}, {%8,%9}, {%0,%1,%2,%3};"
        : "+f"(c[0]), "+f"(c[1]), "+f"(c[2]), "+f"(c[3])
        : "r"(a[0]), "r"(a[1]), "r"(a[2]), "r"(a[3]), "r"(b[0]), "r"(b[1]));
}
__device__ __forceinline__ uint32_t pack_h16(__half a, __half b) {
    __half2 t(a, b);
    return *reinterpret_cast<uint32_t*>(&t);
}

// ---------------------------------------------------------------------------
// Fused prep: X->fp16, W^T->fp16 (smem transpose, coalesced), zero acc+cnt.
// ---------------------------------------------------------------------------
__global__ __launch_bounds__(256) void prep_all(
    const float* __restrict__ X,
    const float* __restrict__ Wq, const float* __restrict__ Wk,
    const float* __restrict__ Wv)
{
    const int bid = blockIdx.x;
    const int tid = threadIdx.x;
    if (bid < PREP_X_BLOCKS) {
        size_t i = ((size_t)bid * 256 + tid) * 4;
        float4 v = *reinterpret_cast<const float4*>(X + i);
        *reinterpret_cast<uint2*>(g_Xh + i) = make_uint2(
            pack_h16(__float2half(v.x), __float2half(v.y)),
            pack_h16(__float2half(v.z), __float2half(v.w)));
    } else if (bid < PREP_X_BLOCKS + PREP_W_BLOCKS) {
        __shared__ float w[64][65];
        int t = bid - PREP_X_BLOCKS;       // 0..191
        int z = t >> 6;
        int tt = t & 63;
        int kb = (tt >> 3) * 64, nb = (tt & 7) * 64;
        const float* W = (z == 0) ? Wq : ((z == 1) ? Wk : Wv);
        // coalesced read 64(k) x 64(n), store transposed into smem
#pragma unroll
        for (int p = 0; p < 4; p++) {
            int r = (tid >> 4) + p * 16;   // k row
            int c = (tid & 15) * 4;        // n col
            float4 v = *reinterpret_cast<const float4*>(W + (size_t)(kb + r) * Cc + nb + c);
            w[c + 0][r] = v.x;
            w[c + 1][r] = v.y;
            w[c + 2][r] = v.z;
            w[c + 3][r] = v.w;
        }
        __syncthreads();
        // coalesced fp16 writes: g_Wth[z][n][k]
#pragma unroll
        for (int p = 0; p < 4; p++) {
            int n = (tid >> 4) + p * 16;
            int k = (tid & 15) * 4;
            uint2 o = make_uint2(
                pack_h16(__float2half(w[n][k + 0]), __float2half(w[n][k + 1])),
                pack_h16(__float2half(w[n][k + 2]), __float2half(w[n][k + 3])));
            *reinterpret_cast<uint2*>(g_Wth + ((size_t)z * Cc + nb + n) * Cc + kb + k) = o;
        }
    } else {
        int i = (bid - PREP_X_BLOCKS - PREP_W_BLOCKS) * 256 + tid;
        if (i < BHn * Dd * Dd) g_KV[i] = 0.f;
        if (i < BHn * Dd)      g_Ksum[i] = 0.f;
        if (i < BHn)           g_cnt[i] = 0;
    }
}

// ---------------------------------------------------------------------------
// Stage 1: QKV fp16 GEMM: out = X @ W (fp32 accum).
// 256-thread CTAs, warp grid 4m x 2n, warp tile 32x64, BK=64, 3-stage ring,
// 2 CTAs/SM. B fragments processed in 2-fragment halves.
// ---------------------------------------------------------------------------
__global__ __launch_bounds__(256, 2) void qkv_gemm_tc(
    const float* __restrict__ bq, const float* __restrict__ bk,
    const float* __restrict__ bv)
{
    extern __shared__ char smem[];
    const uint32_t sbase = smem_u32(smem);
    const int tid = threadIdx.x;
    const int z = blockIdx.x >> 2;
    const int col0 = (blockIdx.x & 3) * 128;
    const int row0 = blockIdx.y * 128;
    const int lane = tid & 31, wid = tid >> 5;
    const int wm = (wid & 3) * 32;
    const int wn = (wid >> 2) * 64;

    const __half* __restrict__ Bh_g = g_Wth + (size_t)z * Cc * Cc;
    const float* __restrict__ bias = (z == 0) ? bq : ((z == 1) ? bk : bv);

    auto issue_half = [&](int kidx, int buf, int half) {
        uint32_t sb = sbase + buf * QSTAGE + (uint32_t)half * 16384;
        int k0 = kidx * 64;
#pragma unroll
        for (int i = 0; i < 4; i++) {
            int idx = tid + i * 256;          // 0..1023
            int r = idx >> 3;
            int c = idx & 7;
            uint32_t off = SWZ128((uint32_t)(r * 128 + c * 16));
            const __half* src = (half == 0)
                ? g_Xh  + (size_t)(row0 + r) * Cc + k0 + c * 8
                : Bh_g  + (size_t)(col0 + r) * Cc + k0 + c * 8;
            cpa16(sb + off, src);
        }
    };

    issue_half(0, 0, 0); issue_half(0, 0, 1); cp_commit();
    issue_half(1, 1, 0); issue_half(1, 1, 1); cp_commit();

    float acc[2][8][4];
#pragma unroll
    for (int i = 0; i < 2; i++)
#pragma unroll
        for (int j = 0; j < 8; j++)
#pragma unroll
            for (int q = 0; q < 4; q++) acc[i][j][q] = 0.f;

    const uint32_t a_k = (uint32_t)((lane >> 4) * 16);
    uint32_t a_rb[2], a_rx[2];
#pragma unroll
    for (int mf = 0; mf < 2; mf++) {
        int ar = wm + mf * 16 + (lane & 15);
        a_rb[mf] = (uint32_t)(ar * 128);
        a_rx[mf] = (uint32_t)((ar & 7) * 16);
    }
    const int b_row_in = (lane & 7) + ((lane >> 4) << 3);
    const uint32_t b_k = (uint32_t)(((lane >> 3) & 1) * 16);
    uint32_t b_rb[4], b_rx[4];
#pragma unroll
    for (int g = 0; g < 4; g++) {
        int br = wn + g * 16 + b_row_in;
        b_rb[g] = (uint32_t)(br * 128) + 16384;
        b_rx[g] = (uint32_t)((br & 7) * 16);
    }

    for (int it = 0; it < QNIT; it++) {
        cp_wait<1>();
        __syncthreads();
        uint32_t sb = sbase + (it % 3) * QSTAGE;
        const bool pre = (it + 2 < QNIT);
        const int pk = it + 2;
        const int pb = (it + 2) % 3;

#pragma unroll
        for (int ks = 0; ks < 4; ks++) {
            const uint32_t kc = (uint32_t)(ks * 32);
            uint32_t ah[2][4];
#pragma unroll
            for (int mf = 0; mf < 2; mf++)
                ldm4(ah[mf], sb + a_rb[mf] + ((kc + a_k) ^ a_rx[mf]));
#pragma unroll
            for (int nh = 0; nh < 2; nh++) {
                uint32_t bh[2][4];
#pragma unroll
                for (int gi = 0; gi < 2; gi++)
                    ldm4(bh[gi], sb + b_rb[nh * 2 + gi] + ((kc + b_k) ^ b_rx[nh * 2 + gi]));
#pragma unroll
                for (int mf = 0; mf < 2; mf++)
#pragma unroll
                    for (int jj = 0; jj < 4; jj++)
                        mma16816h(acc[mf][nh * 4 + jj], ah[mf], &bh[jj >> 1][(jj & 1) * 2]);
            }
            if (pre && ks < 2) issue_half(pk, pb, ks);
            if (ks == 2) cp_commit();
        }
    }

    // Epilogue: bias + feature map (Q,K); all outputs single fp16
    __half* outp = (z == 0) ? g_Q : ((z == 1) ? g_K : g_V);
    const int gq = lane >> 2, tq = lane & 3;
#pragma unroll
    for (int mf = 0; mf < 2; mf++) {
#pragma unroll
        for (int hh = 0; hh < 2; hh++) {
            int mg = row0 + wm + mf * 16 + gq + hh * 8;
#pragma unroll
            for (int j = 0; j < 8; j++) {
                int cg = col0 + wn + j * 8 + tq * 2;
                float v0 = acc[mf][j][hh * 2 + 0] + __ldg(bias + cg);
                float v1 = acc[mf][j][hh * 2 + 1] + __ldg(bias + cg + 1);
                if (z < 2) {
                    v0 = (v0 > 0.f) ? (v0 + 1.f) : __expf(v0);
                    v1 = (v1 > 0.f) ? (v1 + 1.f) : __expf(v1);
                }
                *reinterpret_cast<uint32_t*>(outp + (size_t)mg * Cc + cg) =
                    pack_h16(__float2half(v0), __float2half(v1));
            }
        }
    }
}

// ---------------------------------------------------------------------------
// Stage 2: KV[bh] += K^T V via fp16 tensor cores; Ksum via ones MMA.
// grid (32, 16). Last CTA per bh also writes the transposed fp16 KVt.
// ---------------------------------------------------------------------------
__global__ __launch_bounds__(128) void kv_tc() {
    extern __shared__ char smem[];
    const uint32_t sbase = smem_u32(smem);
    const int bh = blockIdx.x;
    const int b = bh >> 3, h = bh & 7;
    const int s0 = blockIdx.y * 1024;
    const int tid = threadIdx.x;
    const int lane = tid & 31, w = tid >> 5;

    const __half* __restrict__ kf = g_K + ((size_t)(b * Ll + s0)) * Cc + h * 64;
    const __half* __restrict__ vf = g_V + ((size_t)(b * Ll + s0)) * Cc + h * 64;

    auto issue = [&](int st, int buf) {
        uint32_t sb = sbase + buf * KV_STAGE;
#pragma unroll
        for (int i = 0; i < 8; i++) {
            int idx = tid + i * 128;          // 0..1023
            int mat = idx >> 9;
            int row = (idx >> 3) & 63, c16 = idx & 7;
            uint32_t off = SWZ128((uint32_t)(row * 128 + c16 * 16)) + (uint32_t)mat * 8192;
            size_t src = (size_t)(st * 64 + row) * Cc + c16 * 8;
            cpa16(sb + off, (mat ? vf : kf) + src);
        }
        cp_commit();
    };

    issue(0, 0);
    issue(1, 1);

    float accK[8][4], accS[4];
#pragma unroll
    for (int t = 0; t < 8; t++)
#pragma unroll
        for (int q = 0; q < 4; q++) accK[t][q] = 0.f;
#pragma unroll
    for (int q = 0; q < 4; q++) accS[q] = 0.f;

    const uint32_t ones = ((lane >> 2) == 0) ? 0x3C003C00u : 0u;  // fp16 1.0 pair
    uint32_t onef[2] = {ones, ones};

    const uint32_t a_col = (uint32_t)((w * 16 + ((lane >> 4) << 3)) * 2);

    for (int st = 0; st < 16; st++) {
        cp_wait<1>();
        __syncthreads();
        if (st + 2 < 16) issue(st + 2, (st + 2) % 3);
        else cp_commit();

        uint32_t sb = sbase + (st % 3) * KV_STAGE;
#pragma unroll
        for (int s16 = 0; s16 < 4; s16++) {
            uint32_t rowb = (uint32_t)((s16 * 16 + (lane & 15)) * 128);
            uint32_t offA = SWZ128(rowb + a_col);
            uint32_t rk[4];
            ldm4t(rk, sb + offA);
            uint32_t Ah[4] = {rk[0], rk[2], rk[1], rk[3]};
            uint32_t bvf[4][4];
#pragma unroll
            for (int g = 0; g < 4; g++) {
                uint32_t offV = SWZ128(rowb + (uint32_t)((g * 16 + ((lane >> 4) << 3)) * 2));
                ldm4t(bvf[g], sb + 8192 + offV);
            }
#pragma unroll
            for (int t = 0; t < 8; t++)
                mma16816h(accK[t], Ah, &bvf[t >> 1][(t & 1) * 2]);
            mma16816h(accS, Ah, onef);
        }
    }

    const int d0 = w * 16 + (lane >> 2);
    float* KVp = g_KV + (size_t)bh * 4096;
#pragma unroll
    for (int t = 0; t < 8; t++) {
        int v = t * 8 + (lane & 3) * 2;
        atomicAdd(KVp + d0 * 64 + v,           accK[t][0]);
        atomicAdd(KVp + d0 * 64 + v + 1,       accK[t][1]);
        atomicAdd(KVp + (d0 + 8) * 64 + v,     accK[t][2]);
        atomicAdd(KVp + (d0 + 8) * 64 + v + 1, accK[t][3]);
    }
    if ((lane & 3) == 0) {
        atomicAdd(g_Ksum + bh * 64 + d0,     accS[0]);
        atomicAdd(g_Ksum + bh * 64 + d0 + 8, accS[2]);
    }

    // --- last CTA per bh finalizes KVt (transposed fp16 + Ksum row + zeros) ---
    __threadfence();
    __shared__ int isLast;
    if (tid == 0) isLast = (atomicAdd(&g_cnt[bh], 1) == 15);
    __syncthreads();
    if (isLast) {
        float* t = reinterpret_cast<float*>(smem);   // 16KB staging
        const float* kv = g_KV + (size_t)bh * 4096;
#pragma unroll
        for (int i = 0; i < 32; i++)
            t[tid + i * 128] = __ldcg(kv + tid + i * 128);
        __syncthreads();
        __half* oh = g_KVt + (size_t)bh * 80 * 64;
#pragma unroll
        for (int i = 0; i < 32; i++) {
            int j = tid + i * 128;
            oh[j] = __float2half(t[(j & 63) * 64 + (j >> 6)]);
        }
        if (tid < 64) oh[64 * 64 + tid] = __float2half(__ldcg(g_Ksum + bh * 64 + tid));
#pragma unroll
        for (int i = 0; i < 8; i++) {
            int idx = tid + i * 128;
            if (idx < 960) oh[65 * 64 + idx] = __float2half(0.f);
        }
    }
}

// ---------------------------------------------------------------------------
// Stage 3: out = (Q @ KVt) with normalizer from column 64.
// ---------------------------------------------------------------------------
__global__ __launch_bounds__(128) void out_tc(float* __restrict__ out) {
    extern __shared__ char smem[];
    const uint32_t sbase = smem_u32(smem);
    const int bh = blockIdx.x;
    const int b = bh >> 3, h = bh & 7;
    const int l0 = blockIdx.y * 128;
    const int tid = threadIdx.x;
    const int lane = tid & 31, w = tid >> 5;

    {
        const __half* qf = g_Q + ((size_t)(b * Ll + l0)) * Cc + h * 64;
#pragma unroll
        for (int i = 0; i < 8; i++) {
            int idx = tid + i * 128;
            int row = idx >> 3, c16 = idx & 7;
            uint32_t off = SWZ128((uint32_t)(row * 128 + c16 * 16));
            cpa16(sbase + off, qf + (size_t)row * Cc + c16 * 8);
        }
        const __half* bhp = g_KVt + (size_t)bh * 80 * 64;
#pragma unroll
        for (int i = 0; i < 5; i++) {
            int idx = tid + i * 128;
            int row = idx >> 3, c16 = idx & 7;
            uint32_t off = SWZ128((uint32_t)(row * 128 + c16 * 16));
            cpa16(sbase + 16384 + off, bhp + (size_t)row * 64 + c16 * 8);
        }
        cp_commit();
        cp_wait<0>();
        __syncthreads();
    }

    float acc[2][9][4];
#pragma unroll
    for (int im = 0; im < 2; im++)
#pragma unroll
        for (int t = 0; t < 9; t++)
#pragma unroll
            for (int q = 0; q < 4; q++) acc[im][t][q] = 0.f;

    const uint32_t a_k = (uint32_t)((lane >> 4) * 16);
    const int brow = (lane & 7) + ((lane >> 4) << 3);
    const uint32_t b_k = (uint32_t)(((lane >> 3) & 1) * 16);

#pragma unroll
    for (int ks = 0; ks < 4; ks++) {
        uint32_t aH[2][4];
#pragma unroll
        for (int im = 0; im < 2; im++) {
            int ar = w * 32 + im * 16 + (lane & 15);
            uint32_t ka = ((uint32_t)(ks * 32) + a_k) ^ ((uint32_t)((ar & 7) * 16));
            ldm4(aH[im], sbase + (uint32_t)ar * 128 + ka);
        }
        uint32_t bH[5][4];
#pragma unroll
        for (int g = 0; g < 5; g++) {
            int br = g * 16 + brow;
            uint32_t kb = ((uint32_t)(ks * 32) + b_k) ^ ((uint32_t)((br & 7) * 16));
            ldm4(bH[g], sbase + 16384 + (uint32_t)br * 128 + kb);
        }
#pragma unroll
        for (int im = 0; im < 2; im++)
#pragma unroll
            for (int t = 0; t < 9; t++)
                mma16816h(acc[im][t], aH[im], &bH[t >> 1][(t & 1) * 2]);
    }

#pragma unroll
    for (int im = 0; im < 2; im++) {
        float den0 = __shfl_sync(0xffffffffu, acc[im][8][0], lane & ~3);
        float den1 = __shfl_sync(0xffffffffu, acc[im][8][2], lane & ~3);
        float z0 = 1.f / (den0 + 1e-6f);
        float z1 = 1.f / (den1 + 1e-6f);
        int r0 = w * 32 + im * 16 + (lane >> 2);
        float* o0 = out + ((size_t)(b * Ll + l0 + r0)) * Cc + h * 64 + (lane & 3) * 2;
        float* o1 = out + ((size_t)(b * Ll + l0 + r0 + 8)) * Cc + h * 64 + (lane & 3) * 2;
#pragma unroll
        for (int t = 0; t < 8; t++) {
            *reinterpret_cast<float2*>(o0 + t * 8) =
                make_float2(acc[im][t][0] * z0, acc[im][t][1] * z0);
            *reinterpret_cast<float2*>(o1 + t * 8) =
                make_float2(acc[im][t][2] * z1, acc[im][t][3] * z1);
        }
    }
}

// ---------------------------------------------------------------------------
extern "C" void kernel_launch(void* const* d_in, const int* in_sizes, int n_in,
                              void* d_out, int out_size) {
    const float* x  = (const float*)d_in[0];
    const float* Wq = (const float*)d_in[1];
    const float* bq = (const float*)d_in[2];
    const float* Wk = (const float*)d_in[3];
    const float* bk = (const float*)d_in[4];
    const float* Wv = (const float*)d_in[5];
    const float* bv = (const float*)d_in[6];
    float* out = (float*)d_out;

    cudaFuncSetAttribute(qkv_gemm_tc, cudaFuncAttributeMaxDynamicSharedMemorySize, QSMEM);
    cudaFuncSetAttribute(kv_tc, cudaFuncAttributeMaxDynamicSharedMemorySize, KV_SMEM);
    cudaFuncSetAttribute(out_tc, cudaFuncAttributeMaxDynamicSharedMemorySize, OUT_SMEM);

    prep_all<<<PREP_GRID, 256>>>(x, Wq, Wk, Wv);
    qkv_gemm_tc<<<dim3(12, MM / 128), 256, QSMEM>>>(bq, bk, bv);
    kv_tc<<<dim3(BHn, 16), 128, KV_SMEM>>>();
    out_tc<<<dim3(BHn, Ll / 128), 128, OUT_SMEM>>>(out);
}

// round 17
// speedup vs baseline: 1.0221x; 1.0221x over previous
#include <cuda_runtime.h>
#include <cuda_fp16.h>
#include <cstdint>
#include <math.h>

#define Bb 4
#define Ll 16384
#define Cc 512
#define Hh 8
#define Dd 64
#define MM (Bb*Ll)      // 65536
#define BHn (Bb*Hh)     // 32

// Stage-1: 128x128 tile, BK=64, 3 stages, 2 CTA/SM, 256 threads (warp tile 32x64)
#define QSTAGE 32768     // A 16K | B 16K
#define QSMEM (3*QSTAGE)
#define QNIT 8           // 512/64

// kv_tc smem: stage = K 8K | V 8K = 16K, 3 stages
#define KV_STAGE 16384
#define KV_SMEM (3*KV_STAGE)
// out_tc smem: Q 16K | B 10K
#define OUT_SMEM (16384 + 10240)

// fused prep grid split
#define PREP_X_BLOCKS 32768          // MM*Cc/1024
#define PREP_W_BLOCKS 192            // 3 z * 64 (64x64) tiles
#define PREP_Z_BLOCKS 520
#define PREP_GRID (PREP_X_BLOCKS + PREP_W_BLOCKS + PREP_Z_BLOCKS)

// Scratch (all fp16)
__device__ __half g_Xh[(size_t)MM*Cc];            // X
__device__ __half g_Wth[3*(size_t)Cc*Cc];         // W^T, [z][n][k]
__device__ __half g_Q [(size_t)MM*Cc];            // feature-mapped Q
__device__ __half g_K [(size_t)MM*Cc];            // feature-mapped K
__device__ __half g_V [(size_t)MM*Cc];            // V
__device__ float g_KV[BHn*Dd*Dd];
__device__ float g_Ksum[BHn*Dd];
__device__ __half g_KVt[(size_t)BHn*80*64];       // [bh][v-row(80)][d], row64=Ksum

// ---------------------------------------------------------------------------
__device__ __forceinline__ uint32_t smem_u32(const void* p) {
    uint32_t a;
    asm("{ .reg .u64 t; cvta.to.shared.u64 t, %1; cvt.u32.u64 %0, t; }" : "=r"(a) : "l"(p));
    return a;
}
#define SWZ128(o) ((o) ^ (((o) >> 3) & 0x70))

__device__ __forceinline__ void cpa16(uint32_t d, const void* s) {
    uint64_t gp;
    asm("cvta.to.global.u64 %0, %1;" : "=l"(gp) : "l"(s));
    asm volatile("cp.async.cg.shared.global [%0], [%1], 16;" :: "r"(d), "l"(gp) : "memory");
}
__device__ __forceinline__ void cp_commit() {
    asm volatile("cp.async.commit_group;" ::: "memory");
}
template<int N> __device__ __forceinline__ void cp_wait() {
    asm volatile("cp.async.wait_group %0;" :: "n"(N) : "memory");
}
__device__ __forceinline__ void ldm4(uint32_t* r, uint32_t a) {
    asm volatile("ldmatrix.sync.aligned.m8n8.x4.shared.b16 {%0,%1,%2,%3}, [%4];"
        : "=r"(r[0]), "=r"(r[1]), "=r"(r[2]), "=r"(r[3]) : "r"(a));
}
__device__ __forceinline__ void ldm4t(uint32_t* r, uint32_t a) {
    asm volatile("ldmatrix.sync.aligned.m8n8.x4.trans.shared.b16 {%0,%1,%2,%3}, [%4];"
        : "=r"(r[0]), "=r"(r[1]), "=r"(r[2]), "=r"(r[3]) : "r"(a));
}
__device__ __forceinline__ void mma16816h(float* c, const uint32_t* a, const uint32_t* b) {
    asm volatile("mma.sync.aligned.m16n8k16.row.col.f32.f16.f16.f32 "
        "{%0,%1,%2,%3}, {%4,%5,%6,%7}, {%8,%9}, {%0,%1,%2,%3};"
        : "+f"(c[0]), "+f"(c[1]), "+f"(c[2]), "+f"(c[3])
        : "r"(a[0]), "r"(a[1]), "r"(a[2]), "r"(a[3]), "r"(b[0]), "r"(b[1]));
}
__device__ __forceinline__ uint32_t pack_h16(__half a, __half b) {
    __half2 t(a, b);
    return *reinterpret_cast<uint32_t*>(&t);
}

// ---------------------------------------------------------------------------
// Fused prep: X->fp16, W^T->fp16 (smem transpose, coalesced), zero acc.
// ---------------------------------------------------------------------------
__global__ __launch_bounds__(256) void prep_all(
    const float* __restrict__ X,
    const float* __restrict__ Wq, const float* __restrict__ Wk,
    const float* __restrict__ Wv)
{
    const int bid = blockIdx.x;
    const int tid = threadIdx.x;
    if (bid < PREP_X_BLOCKS) {
        size_t i = ((size_t)bid * 256 + tid) * 4;
        float4 v = *reinterpret_cast<const float4*>(X + i);
        *reinterpret_cast<uint2*>(g_Xh + i) = make_uint2(
            pack_h16(__float2half(v.x), __float2half(v.y)),
            pack_h16(__float2half(v.z), __float2half(v.w)));
    } else if (bid < PREP_X_BLOCKS + PREP_W_BLOCKS) {
        __shared__ float w[64][65];
        int t = bid - PREP_X_BLOCKS;       // 0..191
        int z = t >> 6;
        int tt = t & 63;
        int kb = (tt >> 3) * 64, nb = (tt & 7) * 64;
        const float* W = (z == 0) ? Wq : ((z == 1) ? Wk : Wv);
        // coalesced read 64(k) x 64(n), store transposed into smem
#pragma unroll
        for (int p = 0; p < 4; p++) {
            int r = (tid >> 4) + p * 16;   // k row
            int c = (tid & 15) * 4;        // n col
            float4 v = *reinterpret_cast<const float4*>(W + (size_t)(kb + r) * Cc + nb + c);
            w[c + 0][r] = v.x;
            w[c + 1][r] = v.y;
            w[c + 2][r] = v.z;
            w[c + 3][r] = v.w;
        }
        __syncthreads();
        // coalesced fp16 writes: g_Wth[z][n][k]
#pragma unroll
        for (int p = 0; p < 4; p++) {
            int n = (tid >> 4) + p * 16;
            int k = (tid & 15) * 4;
            uint2 o = make_uint2(
                pack_h16(__float2half(w[n][k + 0]), __float2half(w[n][k + 1])),
                pack_h16(__float2half(w[n][k + 2]), __float2half(w[n][k + 3])));
            *reinterpret_cast<uint2*>(g_Wth + ((size_t)z * Cc + nb + n) * Cc + kb + k) = o;
        }
    } else {
        int i = (bid - PREP_X_BLOCKS - PREP_W_BLOCKS) * 256 + tid;
        if (i < BHn * Dd * Dd) g_KV[i] = 0.f;
        if (i < BHn * Dd)      g_Ksum[i] = 0.f;
    }
}

// ---------------------------------------------------------------------------
// Stage 1: QKV fp16 GEMM: out = X @ W (fp32 accum).
// 256-thread CTAs, warp grid 4m x 2n, warp tile 32x64, BK=64, 3-stage ring,
// 2 CTAs/SM. B fragments processed in 2-fragment halves.
// ---------------------------------------------------------------------------
__global__ __launch_bounds__(256, 2) void qkv_gemm_tc(
    const float* __restrict__ bq, const float* __restrict__ bk,
    const float* __restrict__ bv)
{
    extern __shared__ char smem[];
    const uint32_t sbase = smem_u32(smem);
    const int tid = threadIdx.x;
    const int z = blockIdx.x >> 2;
    const int col0 = (blockIdx.x & 3) * 128;
    const int row0 = blockIdx.y * 128;
    const int lane = tid & 31, wid = tid >> 5;
    const int wm = (wid & 3) * 32;
    const int wn = (wid >> 2) * 64;

    const __half* __restrict__ Bh_g = g_Wth + (size_t)z * Cc * Cc;
    const float* __restrict__ bias = (z == 0) ? bq : ((z == 1) ? bk : bv);

    auto issue_half = [&](int kidx, int buf, int half) {
        uint32_t sb = sbase + buf * QSTAGE + (uint32_t)half * 16384;
        int k0 = kidx * 64;
#pragma unroll
        for (int i = 0; i < 4; i++) {
            int idx = tid + i * 256;          // 0..1023
            int r = idx >> 3;
            int c = idx & 7;
            uint32_t off = SWZ128((uint32_t)(r * 128 + c * 16));
            const __half* src = (half == 0)
                ? g_Xh  + (size_t)(row0 + r) * Cc + k0 + c * 8
                : Bh_g  + (size_t)(col0 + r) * Cc + k0 + c * 8;
            cpa16(sb + off, src);
        }
    };

    issue_half(0, 0, 0); issue_half(0, 0, 1); cp_commit();
    issue_half(1, 1, 0); issue_half(1, 1, 1); cp_commit();

    float acc[2][8][4];
#pragma unroll
    for (int i = 0; i < 2; i++)
#pragma unroll
        for (int j = 0; j < 8; j++)
#pragma unroll
            for (int q = 0; q < 4; q++) acc[i][j][q] = 0.f;

    const uint32_t a_k = (uint32_t)((lane >> 4) * 16);
    uint32_t a_rb[2], a_rx[2];
#pragma unroll
    for (int mf = 0; mf < 2; mf++) {
        int ar = wm + mf * 16 + (lane & 15);
        a_rb[mf] = (uint32_t)(ar * 128);
        a_rx[mf] = (uint32_t)((ar & 7) * 16);
    }
    const int b_row_in = (lane & 7) + ((lane >> 4) << 3);
    const uint32_t b_k = (uint32_t)(((lane >> 3) & 1) * 16);
    uint32_t b_rb[4], b_rx[4];
#pragma unroll
    for (int g = 0; g < 4; g++) {
        int br = wn + g * 16 + b_row_in;
        b_rb[g] = (uint32_t)(br * 128) + 16384;
        b_rx[g] = (uint32_t)((br & 7) * 16);
    }

    for (int it = 0; it < QNIT; it++) {
        cp_wait<1>();
        __syncthreads();
        uint32_t sb = sbase + (it % 3) * QSTAGE;
        const bool pre = (it + 2 < QNIT);
        const int pk = it + 2;
        const int pb = (it + 2) % 3;

#pragma unroll
        for (int ks = 0; ks < 4; ks++) {
            const uint32_t kc = (uint32_t)(ks * 32);
            uint32_t ah[2][4];
#pragma unroll
            for (int mf = 0; mf < 2; mf++)
                ldm4(ah[mf], sb + a_rb[mf] + ((kc + a_k) ^ a_rx[mf]));
#pragma unroll
            for (int nh = 0; nh < 2; nh++) {
                uint32_t bh[2][4];
#pragma unroll
                for (int gi = 0; gi < 2; gi++)
                    ldm4(bh[gi], sb + b_rb[nh * 2 + gi] + ((kc + b_k) ^ b_rx[nh * 2 + gi]));
#pragma unroll
                for (int mf = 0; mf < 2; mf++)
#pragma unroll
                    for (int jj = 0; jj < 4; jj++)
                        mma16816h(acc[mf][nh * 4 + jj], ah[mf], &bh[jj >> 1][(jj & 1) * 2]);
            }
            if (pre && ks < 2) issue_half(pk, pb, ks);
            if (ks == 2) cp_commit();
        }
    }

    // Epilogue: bias + feature map (Q,K); all outputs single fp16
    __half* outp = (z == 0) ? g_Q : ((z == 1) ? g_K : g_V);
    const int gq = lane >> 2, tq = lane & 3;
#pragma unroll
    for (int mf = 0; mf < 2; mf++) {
#pragma unroll
        for (int hh = 0; hh < 2; hh++) {
            int mg = row0 + wm + mf * 16 + gq + hh * 8;
#pragma unroll
            for (int j = 0; j < 8; j++) {
                int cg = col0 + wn + j * 8 + tq * 2;
                float v0 = acc[mf][j][hh * 2 + 0] + __ldg(bias + cg);
                float v1 = acc[mf][j][hh * 2 + 1] + __ldg(bias + cg + 1);
                if (z < 2) {
                    v0 = (v0 > 0.f) ? (v0 + 1.f) : __expf(v0);
                    v1 = (v1 > 0.f) ? (v1 + 1.f) : __expf(v1);
                }
                *reinterpret_cast<uint32_t*>(outp + (size_t)mg * Cc + cg) =
                    pack_h16(__float2half(v0), __float2half(v1));
            }
        }
    }
}

// ---------------------------------------------------------------------------
// Stage 2: KV[bh] += K^T V via fp16 tensor cores; Ksum via ones MMA.
// grid (32, 16): s-chunk 1024 rows per CTA.
// ---------------------------------------------------------------------------
__global__ __launch_bounds__(128) void kv_tc() {
    extern __shared__ char smem[];
    const uint32_t sbase = smem_u32(smem);
    const int bh = blockIdx.x;
    const int b = bh >> 3, h = bh & 7;
    const int s0 = blockIdx.y * 1024;
    const int tid = threadIdx.x;
    const int lane = tid & 31, w = tid >> 5;

    const __half* __restrict__ kf = g_K + ((size_t)(b * Ll + s0)) * Cc + h * 64;
    const __half* __restrict__ vf = g_V + ((size_t)(b * Ll + s0)) * Cc + h * 64;

    auto issue = [&](int st, int buf) {
        uint32_t sb = sbase + buf * KV_STAGE;
#pragma unroll
        for (int i = 0; i < 8; i++) {
            int idx = tid + i * 128;          // 0..1023
            int mat = idx >> 9;
            int row = (idx >> 3) & 63, c16 = idx & 7;
            uint32_t off = SWZ128((uint32_t)(row * 128 + c16 * 16)) + (uint32_t)mat * 8192;
            size_t src = (size_t)(st * 64 + row) * Cc + c16 * 8;
            cpa16(sb + off, (mat ? vf : kf) + src);
        }
        cp_commit();
    };

    issue(0, 0);
    issue(1, 1);

    float accK[8][4], accS[4];
#pragma unroll
    for (int t = 0; t < 8; t++)
#pragma unroll
        for (int q = 0; q < 4; q++) accK[t][q] = 0.f;
#pragma unroll
    for (int q = 0; q < 4; q++) accS[q] = 0.f;

    const uint32_t ones = ((lane >> 2) == 0) ? 0x3C003C00u : 0u;  // fp16 1.0 pair
    uint32_t onef[2] = {ones, ones};

    const uint32_t a_col = (uint32_t)((w * 16 + ((lane >> 4) << 3)) * 2);

    for (int st = 0; st < 16; st++) {
        cp_wait<1>();
        __syncthreads();
        if (st + 2 < 16) issue(st + 2, (st + 2) % 3);
        else cp_commit();

        uint32_t sb = sbase + (st % 3) * KV_STAGE;
#pragma unroll
        for (int s16 = 0; s16 < 4; s16++) {
            uint32_t rowb = (uint32_t)((s16 * 16 + (lane & 15)) * 128);
            uint32_t offA = SWZ128(rowb + a_col);
            uint32_t rk[4];
            ldm4t(rk, sb + offA);
            uint32_t Ah[4] = {rk[0], rk[2], rk[1], rk[3]};
            uint32_t bvf[4][4];
#pragma unroll
            for (int g = 0; g < 4; g++) {
                uint32_t offV = SWZ128(rowb + (uint32_t)((g * 16 + ((lane >> 4) << 3)) * 2));
                ldm4t(bvf[g], sb + 8192 + offV);
            }
#pragma unroll
            for (int t = 0; t < 8; t++)
                mma16816h(accK[t], Ah, &bvf[t >> 1][(t & 1) * 2]);
            mma16816h(accS, Ah, onef);
        }
    }

    const int d0 = w * 16 + (lane >> 2);
    float* KVp = g_KV + (size_t)bh * 4096;
#pragma unroll
    for (int t = 0; t < 8; t++) {
        int v = t * 8 + (lane & 3) * 2;
        atomicAdd(KVp + d0 * 64 + v,           accK[t][0]);
        atomicAdd(KVp + d0 * 64 + v + 1,       accK[t][1]);
        atomicAdd(KVp + (d0 + 8) * 64 + v,     accK[t][2]);
        atomicAdd(KVp + (d0 + 8) * 64 + v + 1, accK[t][3]);
    }
    if ((lane & 3) == 0) {
        atomicAdd(g_Ksum + bh * 64 + d0,     accS[0]);
        atomicAdd(g_Ksum + bh * 64 + d0 + 8, accS[2]);
    }
}

// ---------------------------------------------------------------------------
// Finalize: KVt[bh][v][d] = KV[bh][d][v] fp16; row 64 = Ksum; rows 65-79 = 0.
// One 256-thread CTA per bh; smem-staged transpose, fully coalesced.
// ---------------------------------------------------------------------------
__global__ __launch_bounds__(256) void kv_finalize() {
    __shared__ float t[4096];
    const int bh = blockIdx.x;
    const int tid = threadIdx.x;
    const float* kv = g_KV + (size_t)bh * 4096;
    __half* oh = g_KVt + (size_t)bh * 80 * 64;

#pragma unroll
    for (int i = 0; i < 16; i++)
        t[tid + i * 256] = kv[tid + i * 256];
    __syncthreads();

#pragma unroll
    for (int i = 0; i < 16; i++) {
        int j = tid + i * 256;
        int v = j >> 6, d = j & 63;
        oh[j] = __float2half(t[d * 64 + v]);
    }
    if (tid < 64) oh[64 * 64 + tid] = __float2half(g_Ksum[bh * 64 + tid]);
    {
#pragma unroll
        for (int i = 0; i < 4; i++) {
            int idx = tid + i * 256;
            if (idx < 960) oh[65 * 64 + idx] = __float2half(0.f);
        }
    }
}

// ---------------------------------------------------------------------------
// Stage 3: out = (Q @ KVt) with normalizer from column 64.
// ---------------------------------------------------------------------------
__global__ __launch_bounds__(128) void out_tc(float* __restrict__ out) {
    extern __shared__ char smem[];
    const uint32_t sbase = smem_u32(smem);
    const int bh = blockIdx.x;
    const int b = bh >> 3, h = bh & 7;
    const int l0 = blockIdx.y * 128;
    const int tid = threadIdx.x;
    const int lane = tid & 31, w = tid >> 5;

    {
        const __half* qf = g_Q + ((size_t)(b * Ll + l0)) * Cc + h * 64;
#pragma unroll
        for (int i = 0; i < 8; i++) {
            int idx = tid + i * 128;
            int row = idx >> 3, c16 = idx & 7;
            uint32_t off = SWZ128((uint32_t)(row * 128 + c16 * 16));
            cpa16(sbase + off, qf + (size_t)row * Cc + c16 * 8);
        }
        const __half* bhp = g_KVt + (size_t)bh * 80 * 64;
#pragma unroll
        for (int i = 0; i < 5; i++) {
            int idx = tid + i * 128;
            int row = idx >> 3, c16 = idx & 7;
            uint32_t off = SWZ128((uint32_t)(row * 128 + c16 * 16));
            cpa16(sbase + 16384 + off, bhp + (size_t)row * 64 + c16 * 8);
        }
        cp_commit();
        cp_wait<0>();
        __syncthreads();
    }

    float acc[2][9][4];
#pragma unroll
    for (int im = 0; im < 2; im++)
#pragma unroll
        for (int t = 0; t < 9; t++)
#pragma unroll
            for (int q = 0; q < 4; q++) acc[im][t][q] = 0.f;

    const uint32_t a_k = (uint32_t)((lane >> 4) * 16);
    const int brow = (lane & 7) + ((lane >> 4) << 3);
    const uint32_t b_k = (uint32_t)(((lane >> 3) & 1) * 16);

#pragma unroll
    for (int ks = 0; ks < 4; ks++) {
        uint32_t aH[2][4];
#pragma unroll
        for (int im = 0; im < 2; im++) {
            int ar = w * 32 + im * 16 + (lane & 15);
            uint32_t ka = ((uint32_t)(ks * 32) + a_k) ^ ((uint32_t)((ar & 7) * 16));
            ldm4(aH[im], sbase + (uint32_t)ar * 128 + ka);
        }
        uint32_t bH[5][4];
#pragma unroll
        for (int g = 0; g < 5; g++) {
            int br = g * 16 + brow;
            uint32_t kb = ((uint32_t)(ks * 32) + b_k) ^ ((uint32_t)((br & 7) * 16));
            ldm4(bH[g], sbase + 16384 + (uint32_t)br * 128 + kb);
        }
#pragma unroll
        for (int im = 0; im < 2; im++)
#pragma unroll
            for (int t = 0; t < 9; t++)
                mma16816h(acc[im][t], aH[im], &bH[t >> 1][(t & 1) * 2]);
    }

#pragma unroll
    for (int im = 0; im < 2; im++) {
        float den0 = __shfl_sync(0xffffffffu, acc[im][8][0], lane & ~3);
        float den1 = __shfl_sync(0xffffffffu, acc[im][8][2], lane & ~3);
        float z0 = 1.f / (den0 + 1e-6f);
        float z1 = 1.f / (den1 + 1e-6f);
        int r0 = w * 32 + im * 16 + (lane >> 2);
        float* o0 = out + ((size_t)(b * Ll + l0 + r0)) * Cc + h * 64 + (lane & 3) * 2;
        float* o1 = out + ((size_t)(b * Ll + l0 + r0 + 8)) * Cc + h * 64 + (lane & 3) * 2;
#pragma unroll
        for (int t = 0; t < 8; t++) {
            *reinterpret_cast<float2*>(o0 + t * 8) =
                make_float2(acc[im][t][0] * z0, acc[im][t][1] * z0);
            *reinterpret_cast<float2*>(o1 + t * 8) =
                make_float2(acc[im][t][2] * z1, acc[im][t][3] * z1);
        }
    }
}

// ---------------------------------------------------------------------------
extern "C" void kernel_launch(void* const* d_in, const int* in_sizes, int n_in,
                              void* d_out, int out_size) {
    const float* x  = (const float*)d_in[0];
    const float* Wq = (const float*)d_in[1];
    const float* bq = (const float*)d_in[2];
    const float* Wk = (const float*)d_in[3];
    const float* bk = (const float*)d_in[4];
    const float* Wv = (const float*)d_in[5];
    const float* bv = (const float*)d_in[6];
    float* out = (float*)d_out;

    cudaFuncSetAttribute(qkv_gemm_tc, cudaFuncAttributeMaxDynamicSharedMemorySize, QSMEM);
    cudaFuncSetAttribute(kv_tc, cudaFuncAttributeMaxDynamicSharedMemorySize, KV_SMEM);
    cudaFuncSetAttribute(out_tc, cudaFuncAttributeMaxDynamicSharedMemorySize, OUT_SMEM);

    prep_all<<<PREP_GRID, 256>>>(x, Wq, Wk, Wv);
    qkv_gemm_tc<<<dim3(12, MM / 128), 256, QSMEM>>>(bq, bk, bv);
    kv_tc<<<dim3(BHn, 16), 128, KV_SMEM>>>();
    kv_finalize<<<BHn, 256>>>();
    out_tc<<<dim3(BHn, Ll / 128), 128, OUT_SMEM>>>(out);
}